// round 2
// baseline (speedup 1.0000x reference)
#include <cuda_runtime.h>
#include <math.h>

// Problem constants
#define BB 8
#define NN 128
#define HN_ 256
#define HE_ 128
#define NH 8
#define DH_ 32
#define PP 8128
#define BP 65024   // B * P

// Scratch (no cudaMalloc allowed -> __device__ globals)
__device__ float g_n_in[1024 * 256];     // [B*N, HN]   LayerNormed node features
__device__ float g_qkv[1024 * 768];      // [B*N, 3*HN] q|k|v
__device__ float g_e_in[BP * 128];       // [B*P, HE]   LayerNormed edge features
__device__ float g_e_adj[BP * 8];        // [B*P, H]
__device__ float g_attn[1024 * 256];     // [B*N, HN]
__device__ float g_comb[1024 * 256];     // [B*N, HN]

__device__ __forceinline__ int pair_idx(int i, int j) {
    if (i > j) { int t = i; i = j; j = t; }
    return i * (255 - i) / 2 + (j - i - 1);
}

// ---------------------------------------------------------------------------
// K1: node LayerNorm.  grid = 1024 (one row), block = 256 (one col each)
// ---------------------------------------------------------------------------
__global__ void k_node_ln(const float* __restrict__ nf,
                          const float* __restrict__ gn,
                          const float* __restrict__ bn) {
    int row = blockIdx.x;
    int t = threadIdx.x;
    float x = nf[row * 256 + t];
    float s = x, s2 = x * x;
    #pragma unroll
    for (int o = 16; o; o >>= 1) {
        s  += __shfl_xor_sync(0xFFFFFFFFu, s,  o);
        s2 += __shfl_xor_sync(0xFFFFFFFFu, s2, o);
    }
    __shared__ float rs_[8], rs2_[8];
    int w = t >> 5, l = t & 31;
    if (l == 0) { rs_[w] = s; rs2_[w] = s2; }
    __syncthreads();
    float tot = 0.f, tot2 = 0.f;
    #pragma unroll
    for (int i = 0; i < 8; i++) { tot += rs_[i]; tot2 += rs2_[i]; }
    float mean = tot * (1.0f / 256.0f);
    float var  = tot2 * (1.0f / 256.0f) - mean * mean;
    float rstd = rsqrtf(var + 1e-5f);
    g_n_in[row * 256 + t] = (x - mean) * rstd * gn[t] + bn[t];
}

// ---------------------------------------------------------------------------
// K2: qkv GEMM.  n_in[1024,256] @ Wqkv[256,768] + bqkv
// grid = (32 row-tiles of 32, 3 col-tiles of 256), block = 256
// ---------------------------------------------------------------------------
__global__ void k_qkv(const float* __restrict__ W, const float* __restrict__ bias) {
    __shared__ float As[32 * 256];
    int t = threadIdx.x;
    int row0 = blockIdx.x * 32;
    int cb = blockIdx.y * 256;
    for (int i = t; i < 32 * 256; i += 256) As[i] = g_n_in[row0 * 256 + i];
    __syncthreads();
    float acc[32];
    #pragma unroll
    for (int r = 0; r < 32; r++) acc[r] = 0.f;
    for (int k = 0; k < 256; k++) {
        float w = W[k * 768 + cb + t];
        #pragma unroll
        for (int r = 0; r < 32; r++) acc[r] += As[r * 256 + k] * w;
    }
    float bb = bias[cb + t];
    #pragma unroll
    for (int r = 0; r < 32; r++) g_qkv[(row0 + r) * 768 + cb + t] = acc[r] + bb;
}

// ---------------------------------------------------------------------------
// K3: fused edge LayerNorm + e_adj GEMM (+ write e_in).
// grid = 1016 (64 edge rows each), block = 256
// ---------------------------------------------------------------------------
__global__ void k_edge(const float* __restrict__ ef,
                       const float* __restrict__ ge, const float* __restrict__ be,
                       const float* __restrict__ Wea, const float* __restrict__ bea) {
    __shared__ float es[64 * 128];
    __shared__ float wa[128 * 8];
    __shared__ float ges[128], bes[128];
    int t = threadIdx.x;
    int base = blockIdx.x * 64 * 128;

    float4* es4 = (float4*)es;
    const float4* ef4 = (const float4*)(ef + base);
    #pragma unroll
    for (int i = t; i < 2048; i += 256) es4[i] = ef4[i];
    for (int i = t; i < 1024; i += 256) wa[i] = Wea[i];
    if (t < 128) { ges[t] = ge[t]; bes[t] = be[t]; }
    __syncthreads();

    // LayerNorm: warp w handles rows w*8 .. w*8+7; each lane owns 4 contiguous cols
    int w = t >> 5, l = t & 31;
    #pragma unroll
    for (int rr = 0; rr < 8; rr++) {
        int r = w * 8 + rr;
        float4 v = *(float4*)&es[r * 128 + l * 4];
        float s  = v.x + v.y + v.z + v.w;
        float s2 = v.x * v.x + v.y * v.y + v.z * v.z + v.w * v.w;
        #pragma unroll
        for (int o = 16; o; o >>= 1) {
            s  += __shfl_xor_sync(0xFFFFFFFFu, s,  o);
            s2 += __shfl_xor_sync(0xFFFFFFFFu, s2, o);
        }
        float mean = s * (1.0f / 128.0f);
        float var  = s2 * (1.0f / 128.0f) - mean * mean;
        float rstd = rsqrtf(var + 1e-5f);
        int c = l * 4;
        float4 o4;
        o4.x = (v.x - mean) * rstd * ges[c + 0] + bes[c + 0];
        o4.y = (v.y - mean) * rstd * ges[c + 1] + bes[c + 1];
        o4.z = (v.z - mean) * rstd * ges[c + 2] + bes[c + 2];
        o4.w = (v.w - mean) * rstd * ges[c + 3] + bes[c + 3];
        *(float4*)&es[r * 128 + c] = o4;
    }
    __syncthreads();

    // write e_in
    float4* out4 = (float4*)(g_e_in + base);
    #pragma unroll
    for (int i = t; i < 2048; i += 256) out4[i] = es4[i];

    // e_adj: 64 rows x 8 heads
    #pragma unroll
    for (int o = t; o < 512; o += 256) {
        int r = o >> 3, h = o & 7;
        float s = 0.f;
        #pragma unroll 8
        for (int c = 0; c < 128; c++) s += es[r * 128 + c] * wa[c * 8 + h];
        g_e_adj[blockIdx.x * 512 + o] = s + bea[h];
    }
}

// ---------------------------------------------------------------------------
// K4: attention.  grid = B*N = 1024 (one destination node), block = 256.
// warp h <-> head h, lane = d.
// ---------------------------------------------------------------------------
__global__ void k_attn(const float* __restrict__ Wev,
                       const float* __restrict__ bev,
                       const float* __restrict__ mask) {
    int bn = blockIdx.x;
    int b = bn >> 7, n = bn & 127;
    int t = threadIdx.x;
    int h = t >> 5, l = t & 31;

    __shared__ float ps[8 * 128];      // probs per head per neighbor
    __shared__ float eadjs[8 * 128];
    __shared__ float maskv[128];
    __shared__ int   pidx_s[128];
    __shared__ float accE[8 * 128];    // aggregated e_in per head
    __shared__ float anyv_s;

    const float* qkv_b = g_qkv + b * (128 * 768);
    int pbase = b * PP;

    // prologue: pair indices, masks, e_adj staged to smem
    if (t < 128) {
        int m = t;
        float mv = 0.f;
        int p = 0;
        if (m != n) { p = pair_idx(n, m); mv = mask[pbase + p]; }
        maskv[m] = mv;
        pidx_s[m] = p;
    }
    for (int i = t; i < 1024; i += 256) {
        int m = i & 127, hh = i >> 7;
        float ea = 0.f;
        if (m != n) ea = g_e_adj[(pbase + pair_idx(n, m)) * 8 + hh];
        eadjs[hh * 128 + m] = ea;
    }
    float qv = qkv_b[n * 768 + t];   // t == h*32+d
    __syncthreads();

    // logits: warp h computes 128 dot products via shuffle reduce
    const float scale = 0.17677669529663687f;  // 1/sqrt(32)
    #pragma unroll 4
    for (int m = 0; m < 128; m++) {
        float kv = qkv_b[m * 768 + 256 + t];
        float prod = qv * kv;
        #pragma unroll
        for (int o = 16; o; o >>= 1) prod += __shfl_xor_sync(0xFFFFFFFFu, prod, o);
        if (l == 0) {
            float lg;
            if (m == n) lg = -3.0e38f;
            else {
                lg = prod * scale + eadjs[h * 128 + m];
                if (maskv[m] == 0.f) lg = -9e15f;
            }
            ps[h * 128 + m] = lg;
        }
    }
    __syncwarp();

    // softmax per head (warp-local), zeroed if no valid neighbor
    {
        float l0 = ps[h * 128 + l], l1 = ps[h * 128 + l + 32];
        float l2 = ps[h * 128 + l + 64], l3 = ps[h * 128 + l + 96];
        float mx = fmaxf(fmaxf(l0, l1), fmaxf(l2, l3));
        #pragma unroll
        for (int o = 16; o; o >>= 1) mx = fmaxf(mx, __shfl_xor_sync(0xFFFFFFFFu, mx, o));
        float e0 = __expf(l0 - mx), e1 = __expf(l1 - mx);
        float e2 = __expf(l2 - mx), e3 = __expf(l3 - mx);
        float sum = e0 + e1 + e2 + e3;
        float av = maskv[l] + maskv[l + 32] + maskv[l + 64] + maskv[l + 96];
        #pragma unroll
        for (int o = 16; o; o >>= 1) {
            sum += __shfl_xor_sync(0xFFFFFFFFu, sum, o);
            av  += __shfl_xor_sync(0xFFFFFFFFu, av,  o);
        }
        float anyv = (av > 0.f) ? 1.f : 0.f;
        float inv = anyv / sum;
        ps[h * 128 + l]      = e0 * inv;
        ps[h * 128 + l + 32] = e1 * inv;
        ps[h * 128 + l + 64] = e2 * inv;
        ps[h * 128 + l + 96] = e3 * inv;
        if (t == 0) anyv_s = anyv;
    }
    __syncthreads();

    // aggregate e_in across neighbors for ALL 8 heads at once:
    // thread owns column c for 4 heads -> 8 FMAs per loaded e_in float (x2 halves)
    {
        int c = t & 127;
        int hb = (t >> 7) * 4;
        float a0 = 0.f, a1 = 0.f, a2 = 0.f, a3 = 0.f;
        for (int m = 0; m < 128; m++) {
            if (m == n) continue;
            float ev = g_e_in[(pbase + pidx_s[m]) * 128 + c];
            a0 += ps[(hb + 0) * 128 + m] * ev;
            a1 += ps[(hb + 1) * 128 + m] * ev;
            a2 += ps[(hb + 2) * 128 + m] * ev;
            a3 += ps[(hb + 3) * 128 + m] * ev;
        }
        accE[(hb + 0) * 128 + c] = a0;
        accE[(hb + 1) * 128 + c] = a1;
        accE[(hb + 2) * 128 + c] = a2;
        accE[(hb + 3) * 128 + c] = a3;
    }
    __syncthreads();

    // v aggregation + Wev projection of the aggregated edge feature
    float accv = 0.f;
    #pragma unroll 4
    for (int m = 0; m < 128; m++) {
        float vv = qkv_b[m * 768 + 512 + t];
        accv += ps[h * 128 + m] * vv;
    }
    float pr = 0.f;
    #pragma unroll 8
    for (int c = 0; c < 128; c++) pr += accE[h * 128 + c] * Wev[c * 256 + t];
    g_attn[bn * 256 + t] = accv + pr + anyv_s * bev[t];
}

// ---------------------------------------------------------------------------
// K5a: comb = gelu(concat(n_in, attn) @ Wo + bo).  grid = 128 (8 rows each)
// ---------------------------------------------------------------------------
__global__ void k_out1(const float* __restrict__ Wo, const float* __restrict__ bo) {
    __shared__ float cs[8 * 512];
    int row0 = blockIdx.x * 8;
    int t = threadIdx.x;
    for (int i = t; i < 8 * 512; i += 256) {
        int r = i >> 9, c = i & 511;
        cs[i] = (c < 256) ? g_n_in[(row0 + r) * 256 + c]
                          : g_attn[(row0 + r) * 256 + (c - 256)];
    }
    __syncthreads();
    float acc[8];
    #pragma unroll
    for (int r = 0; r < 8; r++) acc[r] = 0.f;
    for (int k = 0; k < 512; k++) {
        float w = Wo[k * 256 + t];
        #pragma unroll
        for (int r = 0; r < 8; r++) acc[r] += cs[r * 512 + k] * w;
    }
    float bb = bo[t];
    #pragma unroll
    for (int r = 0; r < 8; r++) {
        float x = acc[r] + bb;
        float gel = 0.5f * x * (1.0f + erff(x * 0.70710678118654752f));
        g_comb[(row0 + r) * 256 + t] = gel;
    }
}

// ---------------------------------------------------------------------------
// K5b: val/gate = comb @ Wsk + bsk;  out = nf*(1-g) + val*g.  grid = 128
// ---------------------------------------------------------------------------
__global__ void k_out2(const float* __restrict__ Wsk, const float* __restrict__ bsk,
                       const float* __restrict__ nf, float* __restrict__ out) {
    __shared__ float cs[8 * 256];
    int row0 = blockIdx.x * 8;
    int t = threadIdx.x;
    for (int i = t; i < 2048; i += 256) cs[i] = g_comb[row0 * 256 + i];
    __syncthreads();
    float av[8], ag[8];
    #pragma unroll
    for (int r = 0; r < 8; r++) { av[r] = 0.f; ag[r] = 0.f; }
    for (int k = 0; k < 256; k++) {
        float wv = Wsk[k * 512 + t];
        float wg = Wsk[k * 512 + 256 + t];
        #pragma unroll
        for (int r = 0; r < 8; r++) {
            float c = cs[r * 256 + k];
            av[r] += c * wv;
            ag[r] += c * wg;
        }
    }
    float bv = bsk[t], bg = bsk[256 + t];
    #pragma unroll
    for (int r = 0; r < 8; r++) {
        float val  = av[r] + bv;
        float gate = ag[r] + bg;
        float g = 1.0f / (1.0f + __expf(-gate));
        int idx = (row0 + r) * 256 + t;
        out[idx] = nf[idx] * (1.0f - g) + val * g;
    }
}

// ---------------------------------------------------------------------------
extern "C" void kernel_launch(void* const* d_in, const int* in_sizes, int n_in,
                              void* d_out, int out_size) {
    const float* node_feat = (const float*)d_in[0];
    const float* edge_feat = (const float*)d_in[1];
    // d_in[2] x_idx1, d_in[3] x_idx2: guaranteed triu_indices(N,1) -> computed analytically
    const float* mask_valid = (const float*)d_in[4];
    const float* Wqkv = (const float*)d_in[5];
    const float* bqkv = (const float*)d_in[6];
    const float* Wev  = (const float*)d_in[7];
    const float* bev  = (const float*)d_in[8];
    const float* Wea  = (const float*)d_in[9];
    const float* bea  = (const float*)d_in[10];
    const float* Wo   = (const float*)d_in[11];
    const float* bo   = (const float*)d_in[12];
    const float* Wsk  = (const float*)d_in[13];
    const float* bsk  = (const float*)d_in[14];
    const float* gn   = (const float*)d_in[15];
    const float* bn   = (const float*)d_in[16];
    const float* ge   = (const float*)d_in[17];
    const float* be   = (const float*)d_in[18];
    float* out = (float*)d_out;

    k_node_ln<<<1024, 256>>>(node_feat, gn, bn);
    k_qkv<<<dim3(32, 3), 256>>>(Wqkv, bqkv);
    k_edge<<<1016, 256>>>(edge_feat, ge, be, Wea, bea);
    k_attn<<<1024, 256>>>(Wev, bev, mask_valid);
    k_out1<<<128, 256>>>(Wo, bo);
    k_out2<<<128, 256>>>(Wsk, bsk, node_feat, out);
}

// round 5
// speedup vs baseline: 1.2172x; 1.2172x over previous
#include <cuda_runtime.h>
#include <math.h>

// Problem constants
#define BB 8
#define NN 128
#define HN_ 256
#define HE_ 128
#define NH 8
#define DH_ 32
#define PP 8128
#define BP 65024   // B * P

// Scratch (no cudaMalloc allowed -> __device__ globals)
__device__ float g_n_in[1024 * 256];     // [B*N, HN]
__device__ float g_qkv[1024 * 768];      // [B*N, 3*HN]
__device__ float g_e_in[BP * 128];       // [B*P, HE]
__device__ float g_att[64 * 128 * 128];  // [B*H, N, N] adj -> logits -> probs (in place)
__device__ float g_aggE[1024 * 8 * 128]; // [B*N, H, HE] prob-weighted e_in aggregate
__device__ float g_anyv[1024];           // [B*N] any-valid-neighbor flag
__device__ float g_attn[1024 * 256];     // [B*N, HN]
__device__ float g_comb[1024 * 256];     // [B*N, HN]

__device__ __forceinline__ int pair_idx(int i, int j) {
    if (i > j) { int t = i; i = j; j = t; }
    return i * (255 - i) / 2 + (j - i - 1);
}

// ---------------------------------------------------------------------------
// K1: node LayerNorm.  grid = 1024, block = 256
// ---------------------------------------------------------------------------
__global__ void k_node_ln(const float* __restrict__ nf,
                          const float* __restrict__ gn,
                          const float* __restrict__ bn) {
    int row = blockIdx.x;
    int t = threadIdx.x;
    float x = nf[row * 256 + t];
    float s = x, s2 = x * x;
    #pragma unroll
    for (int o = 16; o; o >>= 1) {
        s  += __shfl_xor_sync(0xFFFFFFFFu, s,  o);
        s2 += __shfl_xor_sync(0xFFFFFFFFu, s2, o);
    }
    __shared__ float rs_[8], rs2_[8];
    int w = t >> 5, l = t & 31;
    if (l == 0) { rs_[w] = s; rs2_[w] = s2; }
    __syncthreads();
    float tot = 0.f, tot2 = 0.f;
    #pragma unroll
    for (int i = 0; i < 8; i++) { tot += rs_[i]; tot2 += rs2_[i]; }
    float mean = tot * (1.0f / 256.0f);
    float var  = tot2 * (1.0f / 256.0f) - mean * mean;
    float rstd = rsqrtf(var + 1e-5f);
    g_n_in[row * 256 + t] = (x - mean) * rstd * gn[t] + bn[t];
}

// ---------------------------------------------------------------------------
// K2: qkv GEMM. n_in[1024,256] @ Wqkv[256,768]. grid=(64,3), block=256.
// Block: 16 rows x 256 cols. Thread: 4 rows x 4 cols (float4 W loads).
// ---------------------------------------------------------------------------
__global__ void k_qkv(const float* __restrict__ W, const float* __restrict__ bias) {
    __shared__ float As[16 * 256];
    int t = threadIdx.x;
    int row0 = blockIdx.x * 16;
    int cb = blockIdx.y * 256;
    const float4* a4 = (const float4*)(g_n_in + row0 * 256);
    float4* s4 = (float4*)As;
    #pragma unroll
    for (int i = t; i < 1024; i += 256) s4[i] = a4[i];
    __syncthreads();
    int cg = t & 63;     // cols cg*4 .. cg*4+3
    int rg = t >> 6;     // rows rg*4 .. rg*4+3
    float4 acc[4];
    #pragma unroll
    for (int r = 0; r < 4; r++) acc[r] = make_float4(0.f, 0.f, 0.f, 0.f);
    for (int k = 0; k < 256; k++) {
        float4 w = *(const float4*)&W[k * 768 + cb + cg * 4];
        #pragma unroll
        for (int r = 0; r < 4; r++) {
            float a = As[(rg * 4 + r) * 256 + k];
            acc[r].x += a * w.x; acc[r].y += a * w.y;
            acc[r].z += a * w.z; acc[r].w += a * w.w;
        }
    }
    float4 bb = *(const float4*)&bias[cb + cg * 4];
    #pragma unroll
    for (int r = 0; r < 4; r++) {
        float4 o;
        o.x = acc[r].x + bb.x; o.y = acc[r].y + bb.y;
        o.z = acc[r].z + bb.z; o.w = acc[r].w + bb.w;
        *(float4*)&g_qkv[(row0 + rg * 4 + r) * 768 + cb + cg * 4] = o;
    }
}

// ---------------------------------------------------------------------------
// K3: edge LayerNorm + e_adj scatter into g_att (mask & bias folded in).
// grid = 1016 (64 edge rows, never crosses batch since 8128 = 127*64), block=256
// ---------------------------------------------------------------------------
__global__ void k_edge(const float* __restrict__ ef,
                       const float* __restrict__ ge, const float* __restrict__ be,
                       const float* __restrict__ Wea, const float* __restrict__ bea,
                       const int* __restrict__ i1, const int* __restrict__ i2,
                       const float* __restrict__ mask) {
    __shared__ float es[64 * 128];
    __shared__ float wa[128 * 8];
    __shared__ float ges[128], bes[128];
    __shared__ int s_i[64], s_j[64];
    __shared__ float s_mask[64];
    int t = threadIdx.x;
    int base_row = blockIdx.x * 64;
    int b = base_row / 8128;
    int p0 = base_row - b * 8128;
    int base = base_row * 128;

    float4* es4 = (float4*)es;
    const float4* ef4 = (const float4*)(ef + base);
    #pragma unroll
    for (int i = t; i < 2048; i += 256) es4[i] = ef4[i];
    for (int i = t; i < 1024; i += 256) wa[i] = Wea[i];
    if (t < 128) { ges[t] = ge[t]; bes[t] = be[t]; }
    if (t < 64) {
        int p = p0 + t;
        s_i[t] = i1[p]; s_j[t] = i2[p];
        s_mask[t] = mask[b * PP + p];
    }
    __syncthreads();

    int w = t >> 5, l = t & 31;
    #pragma unroll
    for (int rr = 0; rr < 8; rr++) {
        int r = w * 8 + rr;
        float4 v = *(float4*)&es[r * 128 + l * 4];
        float s  = v.x + v.y + v.z + v.w;
        float s2 = v.x * v.x + v.y * v.y + v.z * v.z + v.w * v.w;
        #pragma unroll
        for (int o = 16; o; o >>= 1) {
            s  += __shfl_xor_sync(0xFFFFFFFFu, s,  o);
            s2 += __shfl_xor_sync(0xFFFFFFFFu, s2, o);
        }
        float mean = s * (1.0f / 128.0f);
        float var  = s2 * (1.0f / 128.0f) - mean * mean;
        float rstd = rsqrtf(var + 1e-5f);
        int c = l * 4;
        float4 o4;
        o4.x = (v.x - mean) * rstd * ges[c + 0] + bes[c + 0];
        o4.y = (v.y - mean) * rstd * ges[c + 1] + bes[c + 1];
        o4.z = (v.z - mean) * rstd * ges[c + 2] + bes[c + 2];
        o4.w = (v.w - mean) * rstd * ges[c + 3] + bes[c + 3];
        *(float4*)&es[r * 128 + c] = o4;
    }
    __syncthreads();

    float4* out4 = (float4*)(g_e_in + base);
    #pragma unroll
    for (int i = t; i < 2048; i += 256) out4[i] = es4[i];

    // e_adj + scatter (both directions), mask folded as -1e20
    #pragma unroll
    for (int o = t; o < 512; o += 256) {
        int r = o >> 3, h = o & 7;
        float s = 0.f;
        #pragma unroll 8
        for (int c = 0; c < 128; c++) s += es[r * 128 + c] * wa[c * 8 + h];
        float val = (s_mask[r] == 0.f) ? -1e20f : (s + bea[h]);
        int ni = s_i[r], nj = s_j[r];
        float* Ab = g_att + (size_t)(b * 8 + h) * 16384;
        Ab[ni * 128 + nj] = val;
        Ab[nj * 128 + ni] = val;
    }
}

// ---------------------------------------------------------------------------
// K4a: logits = adj + scale * Q K^T (diag forced to -1e20).
// grid = 128 (b, h, m-half), block = 256. Thread: 8n x 4m register tile.
// ---------------------------------------------------------------------------
__global__ void k_logits() {
    int bx = blockIdx.x;
    int b = bx >> 4, h = (bx >> 1) & 7, mbase = (bx & 1) * 64;
    __shared__ float Qs[128 * 36];
    __shared__ float Ks[64 * 36];
    int t = threadIdx.x;

    #pragma unroll
    for (int i = t; i < 1024; i += 256) {
        int n = i >> 3, f = i & 7;
        float4 q = *(const float4*)&g_qkv[(size_t)(b * 128 + n) * 768 + h * 32 + f * 4];
        *(float4*)&Qs[n * 36 + f * 4] = q;
    }
    #pragma unroll
    for (int i = t; i < 512; i += 256) {
        int m = i >> 3, f = i & 7;
        float4 kk = *(const float4*)&g_qkv[(size_t)(b * 128 + mbase + m) * 768 + 256 + h * 32 + f * 4];
        *(float4*)&Ks[m * 36 + f * 4] = kk;
    }
    __syncthreads();

    int n0 = (t >> 4) * 8;
    int m0 = t & 15;
    float acc[8][4];
    #pragma unroll
    for (int i = 0; i < 8; i++)
        #pragma unroll
        for (int j = 0; j < 4; j++) acc[i][j] = 0.f;

    #pragma unroll 4
    for (int k = 0; k < 32; k++) {
        float q[8], kv[4];
        #pragma unroll
        for (int i = 0; i < 8; i++) q[i] = Qs[(n0 + i) * 36 + k];
        #pragma unroll
        for (int j = 0; j < 4; j++) kv[j] = Ks[(m0 + 16 * j) * 36 + k];
        #pragma unroll
        for (int i = 0; i < 8; i++)
            #pragma unroll
            for (int j = 0; j < 4; j++) acc[i][j] += q[i] * kv[j];
    }

    const float scale = 0.17677669529663687f;  // 1/sqrt(32)
    float* Lb = g_att + (size_t)(b * 8 + h) * 16384;
    #pragma unroll
    for (int i = 0; i < 8; i++) {
        int n = n0 + i;
        #pragma unroll
        for (int j = 0; j < 4; j++) {
            int m = mbase + m0 + 16 * j;
            float adj = Lb[n * 128 + m];
            Lb[n * 128 + m] = (n == m) ? -1e20f : fmaf(acc[i][j], scale, adj);
        }
    }
}

// ---------------------------------------------------------------------------
// K4b: softmax (probs written in place into g_att) + 8-head e_in aggregation.
// grid = 1024 (one (b,n)), block = 256. Warp h owns head h for the softmax.
// Aggregation: thread = (cg 0..31 [4 cols], head-pair 0..3, m-split 0..1).
// ---------------------------------------------------------------------------
__global__ void k_smx() {
    int bx = blockIdx.x;
    int b = bx >> 7, n = bx & 127;
    int t = threadIdx.x;
    int h = t >> 5, l = t & 31;

    __shared__ float ps[8 * 128];
    __shared__ int pidx_s[128];
    __shared__ float psum[2 * 8 * 128];

    if (t < 128) pidx_s[t] = (t == n) ? 0 : pair_idx(n, t);

    float* Lrow = g_att + ((size_t)(b * 8 + h) * 128 + n) * 128;
    float4 lg = *(const float4*)&Lrow[l * 4];
    float mx = fmaxf(fmaxf(lg.x, lg.y), fmaxf(lg.z, lg.w));
    #pragma unroll
    for (int o = 16; o; o >>= 1) mx = fmaxf(mx, __shfl_xor_sync(0xFFFFFFFFu, mx, o));
    float anyv = (mx > -1e19f) ? 1.f : 0.f;
    float4 e;
    e.x = __expf(lg.x - mx); e.y = __expf(lg.y - mx);
    e.z = __expf(lg.z - mx); e.w = __expf(lg.w - mx);
    float sum = e.x + e.y + e.z + e.w;
    #pragma unroll
    for (int o = 16; o; o >>= 1) sum += __shfl_xor_sync(0xFFFFFFFFu, sum, o);
    float inv = anyv / sum;
    e.x *= inv; e.y *= inv; e.z *= inv; e.w *= inv;
    *(float4*)&ps[h * 128 + l * 4] = e;
    *(float4*)&Lrow[l * 4] = e;               // probs back for the PV GEMM
    if (t == 0) g_anyv[bx] = anyv;
    __syncthreads();

    // e_in aggregation with 2-way m-split
    int cg = t & 31;
    int g2 = t >> 5;
    int hp = (g2 & 3) * 2;
    int ms = g2 >> 2;
    int pbase = b * PP;
    float4 a0 = make_float4(0.f, 0.f, 0.f, 0.f);
    float4 a1 = make_float4(0.f, 0.f, 0.f, 0.f);
    int mbeg = ms * 64;
    #pragma unroll 4
    for (int mm = 0; mm < 64; mm++) {
        int m = mbeg + mm;
        const float4 ev = *(const float4*)&g_e_in[(size_t)(pbase + pidx_s[m]) * 128 + cg * 4];
        float p0 = ps[hp * 128 + m];
        float p1 = ps[(hp + 1) * 128 + m];
        a0.x += p0 * ev.x; a0.y += p0 * ev.y; a0.z += p0 * ev.z; a0.w += p0 * ev.w;
        a1.x += p1 * ev.x; a1.y += p1 * ev.y; a1.z += p1 * ev.z; a1.w += p1 * ev.w;
    }
    *(float4*)&psum[(ms * 8 + hp) * 128 + cg * 4] = a0;
    *(float4*)&psum[(ms * 8 + hp + 1) * 128 + cg * 4] = a1;
    __syncthreads();

    int hh = t >> 5, cc = t & 31;
    float4 r0 = *(float4*)&psum[(hh * 128) + cc * 4];
    float4 r1 = *(float4*)&psum[((8 + hh) * 128) + cc * 4];
    float4 o;
    o.x = r0.x + r1.x; o.y = r0.y + r1.y; o.z = r0.z + r1.z; o.w = r0.w + r1.w;
    *(float4*)&g_aggE[(size_t)bx * 1024 + hh * 128 + cc * 4] = o;
}

// ---------------------------------------------------------------------------
// K4c: vagg = P @ V -> g_attn. grid = 128 (b, h, n-half), block = 256.
// V staged in smem (reused by 64 output rows).
// ---------------------------------------------------------------------------
__global__ void k_vagg() {
    int bx = blockIdx.x;
    int b = bx >> 4, h = (bx >> 1) & 7, nbase = (bx & 1) * 64;
    __shared__ float Ps[64 * 128];   // 32KB
    __shared__ float Vs[128 * 36];   // 18KB
    int t = threadIdx.x;

    const float4* p4 = (const float4*)(g_att + (size_t)(b * 8 + h) * 16384 + nbase * 128);
    float4* ps4 = (float4*)Ps;
    #pragma unroll
    for (int i = t; i < 2048; i += 256) ps4[i] = p4[i];
    #pragma unroll
    for (int i = t; i < 1024; i += 256) {
        int m = i >> 3, f = i & 7;
        float4 v = *(const float4*)&g_qkv[(size_t)(b * 128 + m) * 768 + 512 + h * 32 + f * 4];
        *(float4*)&Vs[m * 36 + f * 4] = v;
    }
    __syncthreads();

    int d = t & 31, ng = t >> 5;
    float acc[8];
    #pragma unroll
    for (int j = 0; j < 8; j++) acc[j] = 0.f;
    #pragma unroll 2
    for (int m = 0; m < 128; m++) {
        float v = Vs[m * 36 + d];
        #pragma unroll
        for (int j = 0; j < 8; j++) acc[j] += Ps[(ng + 8 * j) * 128 + m] * v;
    }
    #pragma unroll
    for (int j = 0; j < 8; j++) {
        int n = nbase + ng + 8 * j;
        g_attn[(size_t)(b * 128 + n) * 256 + h * 32 + d] = acc[j];
    }
}

// ---------------------------------------------------------------------------
// K4d: g_attn += aggE @ Wev (per head column slice) + anyv * bev.
// grid = 128 (8 rows each), block = 256 (t = h*32+d = output column).
// ---------------------------------------------------------------------------
__global__ void k_proj(const float* __restrict__ Wev, const float* __restrict__ bev) {
    __shared__ float aE[8 * 1024];  // 32KB
    int t = threadIdx.x;
    int row0 = blockIdx.x * 8;
    const float4* src = (const float4*)(g_aggE + (size_t)row0 * 1024);
    float4* dst = (float4*)aE;
    #pragma unroll
    for (int i = t; i < 2048; i += 256) dst[i] = src[i];
    __syncthreads();

    int h = t >> 5;
    float acc[8];
    #pragma unroll
    for (int r = 0; r < 8; r++) acc[r] = 0.f;
    #pragma unroll 2
    for (int c = 0; c < 128; c++) {
        float w = Wev[c * 256 + t];
        #pragma unroll
        for (int r = 0; r < 8; r++) acc[r] += aE[r * 1024 + h * 128 + c] * w;
    }
    float bv = bev[t];
    #pragma unroll
    for (int r = 0; r < 8; r++) {
        int bn = row0 + r;
        float any = g_anyv[bn];
        g_attn[(size_t)bn * 256 + t] += acc[r] + any * bv;
    }
}

// ---------------------------------------------------------------------------
// K5a: comb = gelu(concat(n_in, attn) @ Wo + bo). grid = 128 (8 rows), block=256.
// Thread: 2 rows x 4 cols.
// ---------------------------------------------------------------------------
__global__ void k_out1(const float* __restrict__ Wo, const float* __restrict__ bo) {
    __shared__ float cs[8 * 512];
    int row0 = blockIdx.x * 8;
    int t = threadIdx.x;
    #pragma unroll
    for (int i = t; i < 1024; i += 256) {
        int r = i >> 7, f = i & 127;
        float4 v = (f < 64)
            ? *(const float4*)&g_n_in[(size_t)(row0 + r) * 256 + f * 4]
            : *(const float4*)&g_attn[(size_t)(row0 + r) * 256 + (f - 64) * 4];
        *(float4*)&cs[r * 512 + f * 4] = v;
    }
    __syncthreads();

    int cg = t & 63;   // cols cg*4
    int rg = t >> 6;   // rows rg*2, rg*2+1
    float4 acc0 = make_float4(0.f, 0.f, 0.f, 0.f);
    float4 acc1 = make_float4(0.f, 0.f, 0.f, 0.f);
    for (int k = 0; k < 512; k++) {
        float4 w = *(const float4*)&Wo[k * 256 + cg * 4];
        float a0 = cs[(rg * 2) * 512 + k];
        float a1 = cs[(rg * 2 + 1) * 512 + k];
        acc0.x += a0 * w.x; acc0.y += a0 * w.y; acc0.z += a0 * w.z; acc0.w += a0 * w.w;
        acc1.x += a1 * w.x; acc1.y += a1 * w.y; acc1.z += a1 * w.z; acc1.w += a1 * w.w;
    }
    float4 bb = *(const float4*)&bo[cg * 4];
    const float is2 = 0.70710678118654752f;
    float4 o0, o1;
    float x;
    x = acc0.x + bb.x; o0.x = 0.5f * x * (1.f + erff(x * is2));
    x = acc0.y + bb.y; o0.y = 0.5f * x * (1.f + erff(x * is2));
    x = acc0.z + bb.z; o0.z = 0.5f * x * (1.f + erff(x * is2));
    x = acc0.w + bb.w; o0.w = 0.5f * x * (1.f + erff(x * is2));
    x = acc1.x + bb.x; o1.x = 0.5f * x * (1.f + erff(x * is2));
    x = acc1.y + bb.y; o1.y = 0.5f * x * (1.f + erff(x * is2));
    x = acc1.z + bb.z; o1.z = 0.5f * x * (1.f + erff(x * is2));
    x = acc1.w + bb.w; o1.w = 0.5f * x * (1.f + erff(x * is2));
    *(float4*)&g_comb[(size_t)(row0 + rg * 2) * 256 + cg * 4] = o0;
    *(float4*)&g_comb[(size_t)(row0 + rg * 2 + 1) * 256 + cg * 4] = o1;
}

// ---------------------------------------------------------------------------
// K5b: val/gate = comb @ Wsk + bsk; out = nf*(1-g) + val*g. grid=128, block=256.
// Thread: 4 rows x 4 cols (of 512).
// ---------------------------------------------------------------------------
__global__ void k_out2(const float* __restrict__ Wsk, const float* __restrict__ bsk,
                       const float* __restrict__ nf, float* __restrict__ out) {
    __shared__ float cs[8 * 256];
    __shared__ float vs[8 * 512];
    int row0 = blockIdx.x * 8;
    int t = threadIdx.x;
    const float4* src = (const float4*)(g_comb + (size_t)row0 * 256);
    float4* dst = (float4*)cs;
    #pragma unroll
    for (int i = t; i < 512; i += 256) dst[i] = src[i];
    __syncthreads();

    int cg = t & 127;   // cols cg*4 of 512
    int rg = t >> 7;    // rows rg*4 .. rg*4+3
    float4 acc[4];
    #pragma unroll
    for (int r = 0; r < 4; r++) acc[r] = make_float4(0.f, 0.f, 0.f, 0.f);
    for (int k = 0; k < 256; k++) {
        float4 w = *(const float4*)&Wsk[k * 512 + cg * 4];
        #pragma unroll
        for (int r = 0; r < 4; r++) {
            float a = cs[(rg * 4 + r) * 256 + k];
            acc[r].x += a * w.x; acc[r].y += a * w.y;
            acc[r].z += a * w.z; acc[r].w += a * w.w;
        }
    }
    float4 bb = *(const float4*)&bsk[cg * 4];
    #pragma unroll
    for (int r = 0; r < 4; r++) {
        float4 o;
        o.x = acc[r].x + bb.x; o.y = acc[r].y + bb.y;
        o.z = acc[r].z + bb.z; o.w = acc[r].w + bb.w;
        *(float4*)&vs[(rg * 4 + r) * 512 + cg * 4] = o;
    }
    __syncthreads();

    #pragma unroll
    for (int r = 0; r < 8; r++) {
        float val  = vs[r * 512 + t];
        float gate = vs[r * 512 + 256 + t];
        float g = 1.0f / (1.0f + __expf(-gate));
        size_t idx = (size_t)(row0 + r) * 256 + t;
        out[idx] = nf[idx] * (1.0f - g) + val * g;
    }
}

// ---------------------------------------------------------------------------
extern "C" void kernel_launch(void* const* d_in, const int* in_sizes, int n_in,
                              void* d_out, int out_size) {
    const float* node_feat = (const float*)d_in[0];
    const float* edge_feat = (const float*)d_in[1];
    const int* x_idx1 = (const int*)d_in[2];
    const int* x_idx2 = (const int*)d_in[3];
    const float* mask_valid = (const float*)d_in[4];
    const float* Wqkv = (const float*)d_in[5];
    const float* bqkv = (const float*)d_in[6];
    const float* Wev  = (const float*)d_in[7];
    const float* bev  = (const float*)d_in[8];
    const float* Wea  = (const float*)d_in[9];
    const float* bea  = (const float*)d_in[10];
    const float* Wo   = (const float*)d_in[11];
    const float* bo   = (const float*)d_in[12];
    const float* Wsk  = (const float*)d_in[13];
    const float* bsk  = (const float*)d_in[14];
    const float* gn   = (const float*)d_in[15];
    const float* bn   = (const float*)d_in[16];
    const float* ge   = (const float*)d_in[17];
    const float* be   = (const float*)d_in[18];
    float* out = (float*)d_out;

    k_node_ln<<<1024, 256>>>(node_feat, gn, bn);
    k_qkv<<<dim3(64, 3), 256>>>(Wqkv, bqkv);
    k_edge<<<1016, 256>>>(edge_feat, ge, be, Wea, bea, x_idx1, x_idx2, mask_valid);
    k_logits<<<128, 256>>>();
    k_smx<<<1024, 256>>>();
    k_vagg<<<128, 256>>>();
    k_proj<<<128, 256>>>(Wev, bev);
    k_out1<<<128, 256>>>(Wo, bo);
    k_out2<<<128, 256>>>(Wsk, bsk, node_feat, out);
}

// round 8
// speedup vs baseline: 1.6976x; 1.3947x over previous
#include <cuda_runtime.h>
#include <math.h>

// Problem constants
#define BB 8
#define NN 128
#define HN_ 256
#define HE_ 128
#define NH 8
#define DH_ 32
#define PP 8128
#define BP 65024   // B * P

// Scratch (no cudaMalloc allowed -> __device__ globals)
__device__ float g_n_in[1024 * 256];     // [B*N, HN]
__device__ float g_qkv[1024 * 768];      // [B*N, 3*HN]
__device__ float g_e_in[BP * 128];       // [B*P, HE]
__device__ float g_att[64 * 128 * 128];  // [B*H, N, N] adj -> probs (in place)
__device__ float g_aggE[1024 * 8 * 128]; // [B*N, H, HE]
__device__ float g_anyv[1024];           // [B*N]
__device__ float g_attn[1024 * 256];     // [B*N, HN]

__device__ __forceinline__ int pair_idx(int i, int j) {
    if (i > j) { int t = i; i = j; j = t; }
    return i * (255 - i) / 2 + (j - i - 1);
}

// ---------------------------------------------------------------------------
// K1: node LayerNorm.  grid = 1024, block = 256
// ---------------------------------------------------------------------------
__global__ void k_node_ln(const float* __restrict__ nf,
                          const float* __restrict__ gn,
                          const float* __restrict__ bn) {
    int row = blockIdx.x;
    int t = threadIdx.x;
    float x = nf[row * 256 + t];
    float s = x, s2 = x * x;
    #pragma unroll
    for (int o = 16; o; o >>= 1) {
        s  += __shfl_xor_sync(0xFFFFFFFFu, s,  o);
        s2 += __shfl_xor_sync(0xFFFFFFFFu, s2, o);
    }
    __shared__ float rs_[8], rs2_[8];
    int w = t >> 5, l = t & 31;
    if (l == 0) { rs_[w] = s; rs2_[w] = s2; }
    __syncthreads();
    float tot = 0.f, tot2 = 0.f;
    #pragma unroll
    for (int i = 0; i < 8; i++) { tot += rs_[i]; tot2 += rs2_[i]; }
    float mean = tot * (1.0f / 256.0f);
    float var  = tot2 * (1.0f / 256.0f) - mean * mean;
    float rstd = rsqrtf(var + 1e-5f);
    g_n_in[row * 256 + t] = (x - mean) * rstd * gn[t] + bn[t];
}

// ---------------------------------------------------------------------------
// K2: qkv GEMM. n_in[1024,256] @ Wqkv[256,768]. grid=(64,3), block=256.
// ---------------------------------------------------------------------------
__global__ void k_qkv(const float* __restrict__ W, const float* __restrict__ bias) {
    __shared__ float As[16 * 256];
    int t = threadIdx.x;
    int row0 = blockIdx.x * 16;
    int cb = blockIdx.y * 256;
    const float4* a4 = (const float4*)(g_n_in + row0 * 256);
    float4* s4 = (float4*)As;
    #pragma unroll
    for (int i = t; i < 1024; i += 256) s4[i] = a4[i];
    __syncthreads();
    int cg = t & 63;
    int rg = t >> 6;
    float4 acc[4];
    #pragma unroll
    for (int r = 0; r < 4; r++) acc[r] = make_float4(0.f, 0.f, 0.f, 0.f);
    for (int k = 0; k < 256; k++) {
        float4 w = *(const float4*)&W[k * 768 + cb + cg * 4];
        #pragma unroll
        for (int r = 0; r < 4; r++) {
            float a = As[(rg * 4 + r) * 256 + k];
            acc[r].x += a * w.x; acc[r].y += a * w.y;
            acc[r].z += a * w.z; acc[r].w += a * w.w;
        }
    }
    float4 bb = *(const float4*)&bias[cb + cg * 4];
    #pragma unroll
    for (int r = 0; r < 4; r++) {
        float4 o;
        o.x = acc[r].x + bb.x; o.y = acc[r].y + bb.y;
        o.z = acc[r].z + bb.z; o.w = acc[r].w + bb.w;
        *(float4*)&g_qkv[(row0 + rg * 4 + r) * 768 + cb + cg * 4] = o;
    }
}

// ---------------------------------------------------------------------------
// K3: edge LayerNorm + e_adj scatter into g_att (mask & bias folded in).
// grid = 1016 (64 edge rows per block), block = 256.  es padded to 132/row.
// ---------------------------------------------------------------------------
__global__ void k_edge(const float* __restrict__ ef,
                       const float* __restrict__ ge, const float* __restrict__ be,
                       const float* __restrict__ Wea, const float* __restrict__ bea,
                       const int* __restrict__ i1, const int* __restrict__ i2,
                       const float* __restrict__ mask) {
    __shared__ float es[64 * 132];
    __shared__ float wa[128 * 8];
    __shared__ float ges[128], bes[128];
    __shared__ int s_i[64], s_j[64];
    __shared__ float s_mask[64];
    int t = threadIdx.x;
    int base_row = blockIdx.x * 64;
    int b = base_row / 8128;
    int p0 = base_row - b * 8128;
    int base = base_row * 128;

    float4* es4 = (float4*)es;
    const float4* ef4 = (const float4*)(ef + base);
    #pragma unroll
    for (int i = t; i < 2048; i += 256) es4[(i >> 5) * 33 + (i & 31)] = ef4[i];
    for (int i = t; i < 1024; i += 256) wa[i] = Wea[i];
    if (t < 128) { ges[t] = ge[t]; bes[t] = be[t]; }
    if (t < 64) {
        int p = p0 + t;
        s_i[t] = i1[p]; s_j[t] = i2[p];
        s_mask[t] = mask[b * PP + p];
    }
    __syncthreads();

    int w = t >> 5, l = t & 31;
    #pragma unroll
    for (int rr = 0; rr < 8; rr++) {
        int r = w * 8 + rr;
        float4 v = *(float4*)&es[r * 132 + l * 4];
        float s  = v.x + v.y + v.z + v.w;
        float s2 = v.x * v.x + v.y * v.y + v.z * v.z + v.w * v.w;
        #pragma unroll
        for (int o = 16; o; o >>= 1) {
            s  += __shfl_xor_sync(0xFFFFFFFFu, s,  o);
            s2 += __shfl_xor_sync(0xFFFFFFFFu, s2, o);
        }
        float mean = s * (1.0f / 128.0f);
        float var  = s2 * (1.0f / 128.0f) - mean * mean;
        float rstd = rsqrtf(var + 1e-5f);
        int c = l * 4;
        float4 o4;
        o4.x = (v.x - mean) * rstd * ges[c + 0] + bes[c + 0];
        o4.y = (v.y - mean) * rstd * ges[c + 1] + bes[c + 1];
        o4.z = (v.z - mean) * rstd * ges[c + 2] + bes[c + 2];
        o4.w = (v.w - mean) * rstd * ges[c + 3] + bes[c + 3];
        *(float4*)&es[r * 132 + c] = o4;
    }
    __syncthreads();

    float4* out4 = (float4*)(g_e_in + base);
    #pragma unroll
    for (int i = t; i < 2048; i += 256) out4[i] = es4[(i >> 5) * 33 + (i & 31)];

    // e_adj: thread = (row r, head pair q) -> 2 heads, float4 es reads
    {
        int r = t >> 2, q = t & 3;
        float s0 = 0.f, s1 = 0.f;
        #pragma unroll 8
        for (int c4 = 0; c4 < 32; c4++) {
            float4 e4 = *(float4*)&es[r * 132 + c4 * 4];
            int c = c4 * 4;
            float2 w0 = *(float2*)&wa[(c + 0) * 8 + q * 2];
            float2 w1 = *(float2*)&wa[(c + 1) * 8 + q * 2];
            float2 w2 = *(float2*)&wa[(c + 2) * 8 + q * 2];
            float2 w3 = *(float2*)&wa[(c + 3) * 8 + q * 2];
            s0 += e4.x * w0.x + e4.y * w1.x + e4.z * w2.x + e4.w * w3.x;
            s1 += e4.x * w0.y + e4.y * w1.y + e4.z * w2.y + e4.w * w3.y;
        }
        float m = s_mask[r];
        float v0 = (m == 0.f) ? -1e20f : (s0 + bea[q * 2]);
        float v1 = (m == 0.f) ? -1e20f : (s1 + bea[q * 2 + 1]);
        int ni = s_i[r], nj = s_j[r];
        float* Ab0 = g_att + (size_t)(b * 8 + q * 2) * 16384;
        float* Ab1 = Ab0 + 16384;
        Ab0[ni * 128 + nj] = v0;
        Ab0[nj * 128 + ni] = v0;
        Ab1[ni * 128 + nj] = v1;
        Ab1[nj * 128 + ni] = v1;
    }
}

// ---------------------------------------------------------------------------
// K4: fused logits + softmax + P@V.
// grid = 256 (b, h, n-quarter of 32 rows), block = 256.
// Logits: thread tile 4n x 4m; warp = 4 query rows (lanes cover all 128 keys).
// Probs written to Ps (smem) and back to g_att for the e_in aggregation.
// Then V staged into the K smem region and P@V computed.
// ---------------------------------------------------------------------------
__global__ void k_lsm() {
    int bx = blockIdx.x;
    int b = bx >> 5, h = (bx >> 2) & 7, nq = bx & 3;
    int n0 = nq * 32;
    __shared__ float Qs[32 * 36];
    __shared__ float KVs[128 * 36];
    __shared__ float Ps[32 * 132];
    int t = threadIdx.x;

    {   // Q rows n0..n0+31 : exactly one float4 per thread
        int n = t >> 3, f = t & 7;
        float4 q = *(const float4*)&g_qkv[(size_t)(b * 128 + n0 + n) * 768 + h * 32 + f * 4];
        *(float4*)&Qs[n * 36 + f * 4] = q;
    }
    #pragma unroll
    for (int i = t; i < 1024; i += 256) {
        int m = i >> 3, f = i & 7;
        float4 kk = *(const float4*)&g_qkv[(size_t)(b * 128 + m) * 768 + 256 + h * 32 + f * 4];
        *(float4*)&KVs[m * 36 + f * 4] = kk;
    }
    __syncthreads();

    int n_g = t >> 5;   // warp id = query-row group
    int m_g = t & 31;   // lane = key group
    float acc[4][4];
    #pragma unroll
    for (int i = 0; i < 4; i++)
        #pragma unroll
        for (int j = 0; j < 4; j++) acc[i][j] = 0.f;

    #pragma unroll 8
    for (int k = 0; k < 32; k++) {
        float q[4], kv[4];
        #pragma unroll
        for (int i = 0; i < 4; i++) q[i] = Qs[(n_g * 4 + i) * 36 + k];
        #pragma unroll
        for (int j = 0; j < 4; j++) kv[j] = KVs[(m_g * 4 + j) * 36 + k];
        #pragma unroll
        for (int i = 0; i < 4; i++)
            #pragma unroll
            for (int j = 0; j < 4; j++) acc[i][j] += q[i] * kv[j];
    }

    const float scale = 0.17677669529663687f;  // 1/sqrt(32)
    float* Lb = g_att + (size_t)(b * 8 + h) * 16384;
    #pragma unroll
    for (int i = 0; i < 4; i++) {
        int n = n0 + n_g * 4 + i;
        float4 adj = *(const float4*)&Lb[n * 128 + m_g * 4];
        float lg[4];
        lg[0] = (n == m_g * 4 + 0) ? -1e20f : fmaf(acc[i][0], scale, adj.x);
        lg[1] = (n == m_g * 4 + 1) ? -1e20f : fmaf(acc[i][1], scale, adj.y);
        lg[2] = (n == m_g * 4 + 2) ? -1e20f : fmaf(acc[i][2], scale, adj.z);
        lg[3] = (n == m_g * 4 + 3) ? -1e20f : fmaf(acc[i][3], scale, adj.w);
        float mx = fmaxf(fmaxf(lg[0], lg[1]), fmaxf(lg[2], lg[3]));
        #pragma unroll
        for (int o = 16; o; o >>= 1) mx = fmaxf(mx, __shfl_xor_sync(0xFFFFFFFFu, mx, o));
        float anyv = (mx > -1e19f) ? 1.f : 0.f;
        float e0 = __expf(lg[0] - mx), e1 = __expf(lg[1] - mx);
        float e2 = __expf(lg[2] - mx), e3 = __expf(lg[3] - mx);
        float sum = e0 + e1 + e2 + e3;
        #pragma unroll
        for (int o = 16; o; o >>= 1) sum += __shfl_xor_sync(0xFFFFFFFFu, sum, o);
        float inv = anyv / sum;
        float4 p = make_float4(e0 * inv, e1 * inv, e2 * inv, e3 * inv);
        *(float4*)&Ps[(n_g * 4 + i) * 132 + m_g * 4] = p;
        *(float4*)&Lb[n * 128 + m_g * 4] = p;
        if (m_g == 0) g_anyv[b * 128 + n] = anyv;   // identical across h: benign
    }
    __syncthreads();

    // stage V into the K region
    #pragma unroll
    for (int i = t; i < 1024; i += 256) {
        int m = i >> 3, f = i & 7;
        float4 v = *(const float4*)&g_qkv[(size_t)(b * 128 + m) * 768 + 512 + h * 32 + f * 4];
        *(float4*)&KVs[m * 36 + f * 4] = v;
    }
    __syncthreads();

    // P @ V : thread = (row group ng2, dim d); 4 rows each
    {
        int d = t & 31, ng2 = t >> 5;
        float a2[4];
        #pragma unroll
        for (int j = 0; j < 4; j++) a2[j] = 0.f;
        #pragma unroll 4
        for (int m = 0; m < 128; m++) {
            float v = KVs[m * 36 + d];
            #pragma unroll
            for (int j = 0; j < 4; j++) a2[j] += Ps[(ng2 + 8 * j) * 132 + m] * v;
        }
        #pragma unroll
        for (int j = 0; j < 4; j++) {
            int n = n0 + ng2 + 8 * j;
            g_attn[(size_t)(b * 128 + n) * 256 + h * 32 + d] = a2[j];
        }
    }
}

// ---------------------------------------------------------------------------
// K5: e_in aggregation over neighbors (probs read from g_att).
// grid = 1024 (one (b,n)), block = 256.
// ---------------------------------------------------------------------------
__global__ void k_agg() {
    int bx = blockIdx.x;
    int b = bx >> 7, n = bx & 127;
    int t = threadIdx.x;

    __shared__ float ps[8 * 128];
    __shared__ int pidx_s[128];
    __shared__ float psum[2 * 8 * 128];

    if (t < 128) pidx_s[t] = (t == n) ? 0 : pair_idx(n, t);
    {   // load probs: 8 heads x 128, one float4 per thread
        int hh = t >> 5, mg = t & 31;
        const float* Lb = g_att + ((size_t)(b * 8 + hh) * 128 + n) * 128;
        *(float4*)&ps[hh * 128 + mg * 4] = *(const float4*)&Lb[mg * 4];
    }
    __syncthreads();

    int cg = t & 31;
    int g2 = t >> 5;
    int hp = (g2 & 3) * 2;
    int ms = g2 >> 2;
    int pbase = b * PP;
    float4 a0 = make_float4(0.f, 0.f, 0.f, 0.f);
    float4 a1 = make_float4(0.f, 0.f, 0.f, 0.f);
    int mbeg = ms * 64;
    #pragma unroll 4
    for (int mm = 0; mm < 64; mm++) {
        int m = mbeg + mm;
        const float4 ev = *(const float4*)&g_e_in[(size_t)(pbase + pidx_s[m]) * 128 + cg * 4];
        float p0 = ps[hp * 128 + m];
        float p1 = ps[(hp + 1) * 128 + m];
        a0.x += p0 * ev.x; a0.y += p0 * ev.y; a0.z += p0 * ev.z; a0.w += p0 * ev.w;
        a1.x += p1 * ev.x; a1.y += p1 * ev.y; a1.z += p1 * ev.z; a1.w += p1 * ev.w;
    }
    *(float4*)&psum[(ms * 8 + hp) * 128 + cg * 4] = a0;
    *(float4*)&psum[(ms * 8 + hp + 1) * 128 + cg * 4] = a1;
    __syncthreads();

    int hh = t >> 5, cc = t & 31;
    float4 r0 = *(float4*)&psum[(hh * 128) + cc * 4];
    float4 r1 = *(float4*)&psum[((8 + hh) * 128) + cc * 4];
    float4 o;
    o.x = r0.x + r1.x; o.y = r0.y + r1.y; o.z = r0.z + r1.z; o.w = r0.w + r1.w;
    *(float4*)&g_aggE[(size_t)bx * 1024 + hh * 128 + cc * 4] = o;
}

// ---------------------------------------------------------------------------
// K6: g_attn += aggE @ Wev + anyv * bev.  grid = 256 (4 rows each), block=256.
// ---------------------------------------------------------------------------
__global__ void k_proj(const float* __restrict__ Wev, const float* __restrict__ bev) {
    __shared__ float aE[4 * 1024];
    int t = threadIdx.x;
    int row0 = blockIdx.x * 4;
    const float4* src = (const float4*)(g_aggE + (size_t)row0 * 1024);
    float4* dst = (float4*)aE;
    #pragma unroll
    for (int i = t; i < 1024; i += 256) dst[i] = src[i];
    __syncthreads();

    int h = t >> 5;
    float acc[4];
    #pragma unroll
    for (int r = 0; r < 4; r++) acc[r] = 0.f;
    #pragma unroll 4
    for (int c = 0; c < 128; c++) {
        float w = Wev[c * 256 + t];
        #pragma unroll
        for (int r = 0; r < 4; r++) acc[r] += aE[r * 1024 + h * 128 + c] * w;
    }
    float bv = bev[t];
    #pragma unroll
    for (int r = 0; r < 4; r++) {
        int bn = row0 + r;
        float any = g_anyv[bn];
        g_attn[(size_t)bn * 256 + t] += acc[r] + any * bv;
    }
}

// ---------------------------------------------------------------------------
// K7: fused output: comb = gelu(cat(n_in,attn)@Wo+bo); val/gate = comb@Wsk+bsk;
//     out = nf*(1-g) + val*g.   grid = 256 (4 rows each), block = 256.
// ---------------------------------------------------------------------------
__global__ void k_out(const float* __restrict__ Wo, const float* __restrict__ bo,
                      const float* __restrict__ Wsk, const float* __restrict__ bsk,
                      const float* __restrict__ nf, float* __restrict__ out) {
    __shared__ float cs[4 * 512];
    __shared__ float comb[4 * 256];
    __shared__ float vg[4 * 512];
    int row0 = blockIdx.x * 4;
    int t = threadIdx.x;
    #pragma unroll
    for (int i = t; i < 512; i += 256) {
        int r = i >> 7, f = i & 127;
        float4 v = (f < 64)
            ? *(const float4*)&g_n_in[(size_t)(row0 + r) * 256 + f * 4]
            : *(const float4*)&g_attn[(size_t)(row0 + r) * 256 + (f - 64) * 4];
        *(float4*)&cs[r * 512 + f * 4] = v;
    }
    __syncthreads();

    // GEMM1: 4 rows x 256 cols; thread = (row rg, 4 cols)
    {
        int cg = t & 63, rg = t >> 6;
        float4 acc = make_float4(0.f, 0.f, 0.f, 0.f);
        for (int k = 0; k < 512; k++) {
            float4 w = *(const float4*)&Wo[k * 256 + cg * 4];
            float a = cs[rg * 512 + k];
            acc.x += a * w.x; acc.y += a * w.y; acc.z += a * w.z; acc.w += a * w.w;
        }
        float4 bb = *(const float4*)&bo[cg * 4];
        const float is2 = 0.70710678118654752f;
        float x;
        float4 o;
        x = acc.x + bb.x; o.x = 0.5f * x * (1.f + erff(x * is2));
        x = acc.y + bb.y; o.y = 0.5f * x * (1.f + erff(x * is2));
        x = acc.z + bb.z; o.z = 0.5f * x * (1.f + erff(x * is2));
        x = acc.w + bb.w; o.w = 0.5f * x * (1.f + erff(x * is2));
        *(float4*)&comb[rg * 256 + cg * 4] = o;
    }
    __syncthreads();

    // GEMM2: 4 rows x 512 cols; thread = (2 rows, 4 cols)
    {
        int cg = t & 127, rg = t >> 7;
        float4 acc0 = make_float4(0.f, 0.f, 0.f, 0.f);
        float4 acc1 = make_float4(0.f, 0.f, 0.f, 0.f);
        for (int k = 0; k < 256; k++) {
            float4 w = *(const float4*)&Wsk[k * 512 + cg * 4];
            float a0 = comb[(rg * 2) * 256 + k];
            float a1 = comb[(rg * 2 + 1) * 256 + k];
            acc0.x += a0 * w.x; acc0.y += a0 * w.y; acc0.z += a0 * w.z; acc0.w += a0 * w.w;
            acc1.x += a1 * w.x; acc1.y += a1 * w.y; acc1.z += a1 * w.z; acc1.w += a1 * w.w;
        }
        float4 bb = *(const float4*)&bsk[cg * 4];
        float4 o0, o1;
        o0.x = acc0.x + bb.x; o0.y = acc0.y + bb.y; o0.z = acc0.z + bb.z; o0.w = acc0.w + bb.w;
        o1.x = acc1.x + bb.x; o1.y = acc1.y + bb.y; o1.z = acc1.z + bb.z; o1.w = acc1.w + bb.w;
        *(float4*)&vg[(rg * 2) * 512 + cg * 4] = o0;
        *(float4*)&vg[(rg * 2 + 1) * 512 + cg * 4] = o1;
    }
    __syncthreads();

    #pragma unroll
    for (int r = 0; r < 4; r++) {
        float val  = vg[r * 512 + t];
        float gate = vg[r * 512 + 256 + t];
        float g = 1.0f / (1.0f + __expf(-gate));
        size_t idx = (size_t)(row0 + r) * 256 + t;
        out[idx] = nf[idx] * (1.0f - g) + val * g;
    }
}

// ---------------------------------------------------------------------------
extern "C" void kernel_launch(void* const* d_in, const int* in_sizes, int n_in,
                              void* d_out, int out_size) {
    const float* node_feat = (const float*)d_in[0];
    const float* edge_feat = (const float*)d_in[1];
    const int* x_idx1 = (const int*)d_in[2];
    const int* x_idx2 = (const int*)d_in[3];
    const float* mask_valid = (const float*)d_in[4];
    const float* Wqkv = (const float*)d_in[5];
    const float* bqkv = (const float*)d_in[6];
    const float* Wev  = (const float*)d_in[7];
    const float* bev  = (const float*)d_in[8];
    const float* Wea  = (const float*)d_in[9];
    const float* bea  = (const float*)d_in[10];
    const float* Wo   = (const float*)d_in[11];
    const float* bo   = (const float*)d_in[12];
    const float* Wsk  = (const float*)d_in[13];
    const float* bsk  = (const float*)d_in[14];
    const float* gn   = (const float*)d_in[15];
    const float* bn   = (const float*)d_in[16];
    const float* ge   = (const float*)d_in[17];
    const float* be   = (const float*)d_in[18];
    float* out = (float*)d_out;

    k_node_ln<<<1024, 256>>>(node_feat, gn, bn);
    k_qkv<<<dim3(64, 3), 256>>>(Wqkv, bqkv);
    k_edge<<<1016, 256>>>(edge_feat, ge, be, Wea, bea, x_idx1, x_idx2, mask_valid);
    k_lsm<<<256, 256>>>();
    k_agg<<<1024, 256>>>();
    k_proj<<<256, 256>>>(Wev, bev);
    k_out<<<256, 256>>>(Wo, bo, Wsk, bsk, node_feat, out);
}